// round 1
// baseline (speedup 1.0000x reference)
#include <cuda_runtime.h>

// Problem constants (fixed by setup_inputs)
#define BATCH 16
#define NPTS  4096
#define MQ    1024
#define KNB   32
#define ROWS_TOT (BATCH*NPTS)      // 65536 source-point rows
#define BM_TOT   (BATCH*MQ)        // 16384 query points
#define CNT_TOT  (BATCH*MQ*KNB)    // 524288 gathered slots (BN denominator)
#define NBLK_STATS 1024

// ---------------- device scratch (static, no allocation) ----------------
__device__ int d_inds[BM_TOT*KNB];                    // ball-query neighbor indices
__device__ int d_cnt[ROWS_TOT];                       // multiplicity of each (b,n)
__device__ __align__(16) float d_z0[ROWS_TOT*64];     // raw layer-0 output per (b,n)
__device__ __align__(16) float d_z1[ROWS_TOT*64];     // raw layer-1 output
__device__ __align__(16) float d_z2[ROWS_TOT*128];    // raw layer-2 output
__device__ double d_part[NBLK_STATS*256];             // per-block stats partials (s | s2)
__device__ float d_mu[3*128];
__device__ float d_rs[3*128];

// ---------------- kernel 0: zero counters ----------------
__global__ void k_zero()
{
    int i = blockIdx.x*blockDim.x + threadIdx.x;
    if (i < ROWS_TOT) d_cnt[i] = 0;
}

// ---------------- kernel 1: ball query ----------------
// One thread per query point m; all of xyz[b] staged in shared memory.
// Scans n ascending, keeps first K indices with d2 <= R^2 (matches the
// reference's sort-then-truncate of valid indices), pads with the first
// valid index, and bumps multiplicity counters (int atomics: deterministic).
__global__ void k_ballquery(const float* __restrict__ xyz,
                            const float* __restrict__ nxyz)
{
    __shared__ float sx[NPTS], sy[NPTS], sz[NPTS];
    int b = blockIdx.y;
    const float* xb = xyz + (size_t)b*NPTS*3;
    for (int i = threadIdx.x; i < NPTS; i += blockDim.x) {
        sx[i] = xb[3*i+0];
        sy[i] = xb[3*i+1];
        sz[i] = xb[3*i+2];
    }
    __syncthreads();

    int m = blockIdx.x*blockDim.x + threadIdx.x;
    const float* q = nxyz + ((size_t)b*MQ + m)*3;
    float qx = q[0], qy = q[1], qz = q[2];
    float qn = qx*qx + qy*qy + qz*qz;

    int* my = d_inds + ((size_t)b*MQ + m)*KNB;
    int cnt = 0;
    int first = NPTS - 1;   // mimics JAX gather clamp if (impossibly) no hit
    for (int n = 0; n < NPTS; n++) {
        float px = sx[n], py = sy[n], pz = sz[n];
        float pn  = px*px + py*py + pz*pz;
        float dot = qx*px + qy*py + qz*pz;
        float d2  = qn + pn - 2.0f*dot;
        if (d2 <= 0.25f) {
            if (cnt == 0) first = n;
            my[cnt] = n;
            atomicAdd(&d_cnt[b*NPTS + n], 1);
            if (++cnt == KNB) break;
        }
    }
    for (int j = cnt; j < KNB; j++) my[j] = first;
    if (cnt < KNB) atomicAdd(&d_cnt[b*NPTS + first], KNB - cnt);
}

// ---------------- MLP layer: per-source-point GEMM ----------------
// LAYER 0: feat = concat(xyz, points)            (CIN=67) -> d_z0
// LAYER 1: feat = relu(affine0(d_z0))            (CIN=64) -> d_z1
// LAYER 2: feat = relu(affine1(d_z1))            (CIN=64) -> d_z2
// 256 threads: each thread owns one output channel o and RPT rows;
// weights live in registers, features in shared (broadcast LDS.128).
template<int CIN, int COUT, int RPT, int LAYER>
__global__ __launch_bounds__(256)
void k_mlp(const float* __restrict__ W,
           const float* __restrict__ ga, const float* __restrict__ be,
           const float* __restrict__ xyz, const float* __restrict__ pts)
{
    constexpr int CP4 = (CIN + 3) / 4;
    constexpr int CP  = CP4 * 4;
    constexpr int GROUPS = 256 / COUT;
    constexpr int ROWS = GROUPS * RPT;

    const float* zin = (LAYER == 2) ? d_z1 : d_z0;       // unused for LAYER 0
    float* zout = (LAYER == 0) ? d_z0 : ((LAYER == 1) ? d_z1 : d_z2);
    const float* mu = d_mu + (LAYER - 1) * 128;           // unused for LAYER 0
    const float* rs = d_rs + (LAYER - 1) * 128;

    __shared__ __align__(16) float sfeat[ROWS * CP];
    int tid  = threadIdx.x;
    int row0 = blockIdx.x * ROWS;

    // cooperative feature staging
    for (int idx = tid; idx < ROWS * CP; idx += 256) {
        int r = idx / CP, c = idx % CP;
        int row = row0 + r;
        float v = 0.f;
        if (LAYER == 0) {
            if (c < 3)        v = xyz[(size_t)row*3 + c];
            else if (c < 67)  v = pts[(size_t)row*64 + (c - 3)];
        } else {
            if (c < CIN) {
                float a = rs[c] * ga[c];
                v = fmaxf(0.f, fmaf(zin[(size_t)row*CIN + c] - mu[c], a, be[c]));
            }
        }
        sfeat[idx] = v;
    }

    // load this thread's weight row into registers (zero-padded)
    int o  = tid % COUT;
    int rg = tid / COUT;
    float4 wreg[CP4];
#pragma unroll
    for (int i = 0; i < CP4; i++) {
        float4 w;
        w.x = (4*i+0 < CIN) ? W[o*CIN + 4*i+0] : 0.f;
        w.y = (4*i+1 < CIN) ? W[o*CIN + 4*i+1] : 0.f;
        w.z = (4*i+2 < CIN) ? W[o*CIN + 4*i+2] : 0.f;
        w.w = (4*i+3 < CIN) ? W[o*CIN + 4*i+3] : 0.f;
        wreg[i] = w;
    }
    __syncthreads();

    float acc[RPT];
#pragma unroll
    for (int j = 0; j < RPT; j++) acc[j] = 0.f;

#pragma unroll
    for (int i = 0; i < CP4; i++) {
        float4 w = wreg[i];
#pragma unroll
        for (int j = 0; j < RPT; j++) {
            const float4 f = *reinterpret_cast<const float4*>(
                &sfeat[(rg*RPT + j)*CP + 4*i]);
            acc[j] = fmaf(w.x, f.x, acc[j]);
            acc[j] = fmaf(w.y, f.y, acc[j]);
            acc[j] = fmaf(w.z, f.z, acc[j]);
            acc[j] = fmaf(w.w, f.w, acc[j]);
        }
    }
#pragma unroll
    for (int j = 0; j < RPT; j++)
        zout[(size_t)(row0 + rg*RPT + j)*COUT + o] = acc[j];
}

// ---------------- count-weighted BN statistics ----------------
// Pass A: 1024 blocks produce per-block double partials (deterministic order).
template<int COUT, int LAYER>
__global__ __launch_bounds__(256)
void k_stats()
{
    const float* z = (LAYER == 0) ? d_z0 : ((LAYER == 1) ? d_z1 : d_z2);
    constexpr int G  = 256 / COUT;
    constexpr int RB = ROWS_TOT / NBLK_STATS;   // 64 rows per block
    int tid = threadIdx.x;
    int o   = tid % COUT;
    int r0  = tid / COUT;

    double s = 0.0, s2 = 0.0;
    for (int r = r0; r < RB; r += G) {
        int row = blockIdx.x*RB + r;
        double w = (double)d_cnt[row];
        double v = (double)z[(size_t)row*COUT + o];
        s  += w * v;
        s2 += w * v * v;
    }
    __shared__ double ss[256], ss2[256];
    ss[tid] = s; ss2[tid] = s2;
    __syncthreads();
    if (tid < COUT) {
        double ts = 0.0, t2 = 0.0;
        for (int g = 0; g < G; g++) { ts += ss[tid + g*COUT]; t2 += ss2[tid + g*COUT]; }
        d_part[blockIdx.x*256 + tid]       = ts;
        d_part[blockIdx.x*256 + 128 + tid] = t2;
    }
}

// Pass B: fixed-order reduction over block partials -> mu, rsigma.
template<int COUT>
__global__ void k_finalize(int layer)
{
    int c = threadIdx.x;
    if (c >= COUT) return;
    double s = 0.0, s2 = 0.0;
    for (int b = 0; b < NBLK_STATS; b++) {
        s  += d_part[b*256 + c];
        s2 += d_part[b*256 + 128 + c];
    }
    double mu  = s / (double)CNT_TOT;
    double var = s2 / (double)CNT_TOT - mu*mu;
    d_mu[layer*128 + c] = (float)mu;
    d_rs[layer*128 + c] = (float)(1.0 / sqrt(var + 1e-5));
}

// ---------------- max-pool + final BN + ReLU ----------------
// One warp per (b,m): running min AND max of raw z2 over the 32 neighbors,
// then pick by sign of a = rs*g so affine+relu commutes with the pool exactly.
__global__ __launch_bounds__(256)
void k_maxpool(const float* __restrict__ g2, const float* __restrict__ b2,
               float* __restrict__ out)
{
    int warp = (blockIdx.x*blockDim.x + threadIdx.x) >> 5;
    int lane = threadIdx.x & 31;
    int b = warp / MQ;
    int myind = d_inds[warp*KNB + lane];

    float4 mx = make_float4(-3.4e38f, -3.4e38f, -3.4e38f, -3.4e38f);
    float4 mn = make_float4( 3.4e38f,  3.4e38f,  3.4e38f,  3.4e38f);
    const float4* zb = reinterpret_cast<const float4*>(d_z2) + (size_t)b*NPTS*32;
#pragma unroll 8
    for (int k = 0; k < KNB; k++) {
        int n = __shfl_sync(0xffffffffu, myind, k);
        float4 v = zb[(size_t)n*32 + lane];
        mx.x = fmaxf(mx.x, v.x); mx.y = fmaxf(mx.y, v.y);
        mx.z = fmaxf(mx.z, v.z); mx.w = fmaxf(mx.w, v.w);
        mn.x = fminf(mn.x, v.x); mn.y = fminf(mn.y, v.y);
        mn.z = fminf(mn.z, v.z); mn.w = fminf(mn.w, v.w);
    }

    int cbase = lane*4;
    float vmx[4] = {mx.x, mx.y, mx.z, mx.w};
    float vmn[4] = {mn.x, mn.y, mn.z, mn.w};
    float4 r;
    float* rp = &r.x;
#pragma unroll
    for (int j = 0; j < 4; j++) {
        int c = cbase + j;
        float a  = d_rs[2*128 + c] * g2[c];
        float v  = (a >= 0.f) ? vmx[j] : vmn[j];
        rp[j] = fmaxf(0.f, fmaf(v - d_mu[2*128 + c], a, b2[c]));
    }
    reinterpret_cast<float4*>(out)[(size_t)warp*32 + lane] = r;
}

// ---------------- copy new_xyz into output head ----------------
__global__ void k_copy(const float* __restrict__ nxyz, float* __restrict__ out)
{
    int i = blockIdx.x*blockDim.x + threadIdx.x;
    if (i < BM_TOT*3) out[i] = nxyz[i];
}

// ---------------- launch ----------------
extern "C" void kernel_launch(void* const* d_in, const int* in_sizes, int n_in,
                              void* d_out, int out_size)
{
    const float* xyz    = (const float*)d_in[0];
    const float* points = (const float*)d_in[1];
    const float* nxyz   = (const float*)d_in[2];
    const float* W0     = (const float*)d_in[3];
    const float* g0     = (const float*)d_in[4];
    const float* b0     = (const float*)d_in[5];
    const float* W1     = (const float*)d_in[6];
    const float* g1     = (const float*)d_in[7];
    const float* b1     = (const float*)d_in[8];
    const float* W2     = (const float*)d_in[9];
    const float* g2     = (const float*)d_in[10];
    const float* b2     = (const float*)d_in[11];
    float* out = (float*)d_out;

    k_zero<<<ROWS_TOT/256, 256>>>();
    k_ballquery<<<dim3(MQ/128, BATCH), 128>>>(xyz, nxyz);

    // layer 0: 67 -> 64
    k_mlp<67, 64, 4, 0><<<ROWS_TOT/16, 256>>>(W0, nullptr, nullptr, xyz, points);
    k_stats<64, 0><<<NBLK_STATS, 256>>>();
    k_finalize<64><<<1, 128>>>(0);

    // layer 1: 64 -> 64 (applies affine0+relu on load)
    k_mlp<64, 64, 4, 1><<<ROWS_TOT/16, 256>>>(W1, g0, b0, nullptr, nullptr);
    k_stats<64, 1><<<NBLK_STATS, 256>>>();
    k_finalize<64><<<1, 128>>>(1);

    // layer 2: 64 -> 128 (applies affine1+relu on load)
    k_mlp<64, 128, 8, 2><<<ROWS_TOT/16, 256>>>(W2, g1, b1, nullptr, nullptr);
    k_stats<128, 2><<<NBLK_STATS, 256>>>();
    k_finalize<128><<<1, 128>>>(2);

    // pool + final BN/relu, and new_xyz passthrough
    k_maxpool<<<BM_TOT/8, 256>>>(g2, b2, out + (size_t)BM_TOT*3);
    k_copy<<<(BM_TOT*3 + 255)/256, 256>>>(nxyz, out);
}

// round 3
// speedup vs baseline: 1.0878x; 1.0878x over previous
#include <cuda_runtime.h>

// Problem constants (fixed by setup_inputs)
#define BATCH 16
#define NPTS  4096
#define MQ    1024
#define KNB   32
#define ROWS_TOT (BATCH*NPTS)      // 65536 source-point rows
#define BM_TOT   (BATCH*MQ)        // 16384 query points
#define CNT_TOT  (BATCH*MQ*KNB)    // 524288 gathered slots (BN denominator)
#define NBLK_STATS 1024

// ---------------- device scratch (static, no allocation) ----------------
__device__ int d_inds[BM_TOT*KNB];                    // ball-query neighbor indices
__device__ int d_cnt[ROWS_TOT];                       // multiplicity of each (b,n)
__device__ float d_sx[ROWS_TOT], d_sy[ROWS_TOT], d_sz[ROWS_TOT], d_pn[ROWS_TOT];
__device__ __align__(16) float d_z0[ROWS_TOT*64];     // raw layer-0 output per (b,n)
__device__ __align__(16) float d_z1[ROWS_TOT*64];     // raw layer-1 output
__device__ __align__(16) float d_z2[ROWS_TOT*128];    // raw layer-2 output
__device__ double d_part[NBLK_STATS*256];             // per-block stats partials (s | s2)
__device__ float d_mu[3*128];
__device__ float d_rs[3*128];

// ---------------- kernel 0: SoA transpose + |p|^2 + zero counters ----------------
__global__ void k_prep(const float* __restrict__ xyz)
{
    int i = blockIdx.x*blockDim.x + threadIdx.x;
    if (i >= ROWS_TOT) return;
    float x = xyz[3*i+0], y = xyz[3*i+1], z = xyz[3*i+2];
    d_sx[i] = x; d_sy[i] = y; d_sz[i] = z;
    d_pn[i] = x*x + y*y + z*z;
    d_cnt[i] = 0;
}

// ---------------- kernel 1: ball query (warp per query) ----------------
// Each warp scans n in ascending 32-wide steps. Ballot + prefix-popc gives
// each accepted hit its ascending-order slot (matches reference's
// sort-then-truncate). Warp-uniform early exit once 32 slots are filled.
__global__ __launch_bounds__(256)
void k_ballquery(const float* __restrict__ nxyz)
{
    int lane = threadIdx.x & 31;
    int q = (blockIdx.x*blockDim.x + threadIdx.x) >> 5;   // query id in [0, BM_TOT)
    int b = q / MQ;
    int nb = b * NPTS;

    const float* qp = nxyz + (size_t)q*3;
    float qx = qp[0], qy = qp[1], qz = qp[2];
    float qn = qx*qx + qy*qy + qz*qz;

    int* my = d_inds + (size_t)q*KNB;
    int cnt = 0;
    int first = NPTS - 1;
    bool have_first = false;

    for (int base = 0; base < NPTS; base += 32) {
        int n = base + lane;
        float d2 = fmaf(-2.0f*qx, d_sx[nb+n],
                   fmaf(-2.0f*qy, d_sy[nb+n],
                   fmaf(-2.0f*qz, d_sz[nb+n], qn + d_pn[nb+n])));
        bool hit = d2 <= 0.25f;
        unsigned msk = __ballot_sync(0xffffffffu, hit);
        int pos = cnt + __popc(msk & ((1u << lane) - 1u));
        if (hit && pos < KNB) {
            my[pos] = n;
            atomicAdd(&d_cnt[nb+n], 1);
        }
        if (!have_first && msk) { first = base + __ffs(msk) - 1; have_first = true; }
        cnt += __popc(msk);
        if (cnt >= KNB) break;
    }

    if (cnt < KNB) {
        if (lane >= cnt) my[lane] = first;
        if (lane == 0) atomicAdd(&d_cnt[nb+first], KNB - cnt);
    }
}

// ---------------- MLP layer: per-source-point GEMM ----------------
// LAYER 0: feat = concat(xyz, points)            (CIN=67) -> d_z0
// LAYER 1: feat = relu(affine0(d_z0))            (CIN=64) -> d_z1
// LAYER 2: feat = relu(affine1(d_z1))            (CIN=64) -> d_z2
// 256 threads: each thread owns one output channel o and RPT rows;
// weights live in registers, features in shared (broadcast LDS.128).
template<int CIN, int COUT, int RPT, int LAYER>
__global__ __launch_bounds__(256)
void k_mlp(const float* __restrict__ W,
           const float* __restrict__ ga, const float* __restrict__ be,
           const float* __restrict__ xyz, const float* __restrict__ pts)
{
    constexpr int CP4 = (CIN + 3) / 4;
    constexpr int CP  = CP4 * 4;
    constexpr int GROUPS = 256 / COUT;
    constexpr int ROWS = GROUPS * RPT;

    const float* zin = (LAYER == 2) ? d_z1 : d_z0;       // unused for LAYER 0
    float* zout = (LAYER == 0) ? d_z0 : ((LAYER == 1) ? d_z1 : d_z2);
    const float* mu = d_mu + (LAYER - 1) * 128;           // unused for LAYER 0
    const float* rs = d_rs + (LAYER - 1) * 128;

    __shared__ __align__(16) float sfeat[ROWS * CP];
    int tid  = threadIdx.x;
    int row0 = blockIdx.x * ROWS;

    // cooperative feature staging
    for (int idx = tid; idx < ROWS * CP; idx += 256) {
        int r = idx / CP, c = idx % CP;
        int row = row0 + r;
        float v = 0.f;
        if (LAYER == 0) {
            if (c < 3)        v = xyz[(size_t)row*3 + c];
            else if (c < 67)  v = pts[(size_t)row*64 + (c - 3)];
        } else {
            if (c < CIN) {
                float a = rs[c] * ga[c];
                v = fmaxf(0.f, fmaf(zin[(size_t)row*CIN + c] - mu[c], a, be[c]));
            }
        }
        sfeat[idx] = v;
    }

    // load this thread's weight row into registers (zero-padded)
    int o  = tid % COUT;
    int rg = tid / COUT;
    float4 wreg[CP4];
#pragma unroll
    for (int i = 0; i < CP4; i++) {
        float4 w;
        w.x = (4*i+0 < CIN) ? W[o*CIN + 4*i+0] : 0.f;
        w.y = (4*i+1 < CIN) ? W[o*CIN + 4*i+1] : 0.f;
        w.z = (4*i+2 < CIN) ? W[o*CIN + 4*i+2] : 0.f;
        w.w = (4*i+3 < CIN) ? W[o*CIN + 4*i+3] : 0.f;
        wreg[i] = w;
    }
    __syncthreads();

    float acc[RPT];
#pragma unroll
    for (int j = 0; j < RPT; j++) acc[j] = 0.f;

#pragma unroll
    for (int i = 0; i < CP4; i++) {
        float4 w = wreg[i];
#pragma unroll
        for (int j = 0; j < RPT; j++) {
            const float4 f = *reinterpret_cast<const float4*>(
                &sfeat[(rg*RPT + j)*CP + 4*i]);
            acc[j] = fmaf(w.x, f.x, acc[j]);
            acc[j] = fmaf(w.y, f.y, acc[j]);
            acc[j] = fmaf(w.z, f.z, acc[j]);
            acc[j] = fmaf(w.w, f.w, acc[j]);
        }
    }
#pragma unroll
    for (int j = 0; j < RPT; j++)
        zout[(size_t)(row0 + rg*RPT + j)*COUT + o] = acc[j];
}

// ---------------- count-weighted BN statistics ----------------
// Pass A: 1024 blocks produce per-block double partials (deterministic order).
template<int COUT, int LAYER>
__global__ __launch_bounds__(256)
void k_stats()
{
    const float* z = (LAYER == 0) ? d_z0 : ((LAYER == 1) ? d_z1 : d_z2);
    constexpr int G  = 256 / COUT;
    constexpr int RB = ROWS_TOT / NBLK_STATS;   // 64 rows per block
    int tid = threadIdx.x;
    int o   = tid % COUT;
    int r0  = tid / COUT;

    double s = 0.0, s2 = 0.0;
    for (int r = r0; r < RB; r += G) {
        int row = blockIdx.x*RB + r;
        double w = (double)d_cnt[row];
        double v = (double)z[(size_t)row*COUT + o];
        s  += w * v;
        s2 += w * v * v;
    }
    __shared__ double ss[256], ss2[256];
    ss[tid] = s; ss2[tid] = s2;
    __syncthreads();
    if (tid < COUT) {
        double ts = 0.0, t2 = 0.0;
        for (int g = 0; g < G; g++) { ts += ss[tid + g*COUT]; t2 += ss2[tid + g*COUT]; }
        d_part[blockIdx.x*256 + tid]       = ts;
        d_part[blockIdx.x*256 + 128 + tid] = t2;
    }
}

// Pass B: fixed-order reduction over block partials -> mu, rsigma.
template<int COUT>
__global__ void k_finalize(int layer)
{
    int c = threadIdx.x;
    if (c >= COUT) return;
    double s = 0.0, s2 = 0.0;
    for (int b = 0; b < NBLK_STATS; b++) {
        s  += d_part[b*256 + c];
        s2 += d_part[b*256 + 128 + c];
    }
    double mu  = s / (double)CNT_TOT;
    double var = s2 / (double)CNT_TOT - mu*mu;
    d_mu[layer*128 + c] = (float)mu;
    d_rs[layer*128 + c] = (float)(1.0 / sqrt(var + 1e-5));
}

// ---------------- max-pool + final BN + ReLU ----------------
// One warp per (b,m): running min AND max of raw z2 over the 32 neighbors,
// then pick by sign of a = rs*g so affine+relu commutes with the pool exactly.
__global__ __launch_bounds__(256)
void k_maxpool(const float* __restrict__ g2, const float* __restrict__ b2,
               float* __restrict__ out)
{
    int warp = (blockIdx.x*blockDim.x + threadIdx.x) >> 5;
    int lane = threadIdx.x & 31;
    int b = warp / MQ;
    int myind = d_inds[warp*KNB + lane];

    float4 mx = make_float4(-3.4e38f, -3.4e38f, -3.4e38f, -3.4e38f);
    float4 mn = make_float4( 3.4e38f,  3.4e38f,  3.4e38f,  3.4e38f);
    const float4* zb = reinterpret_cast<const float4*>(d_z2) + (size_t)b*NPTS*32;
#pragma unroll 8
    for (int k = 0; k < KNB; k++) {
        int n = __shfl_sync(0xffffffffu, myind, k);
        float4 v = zb[(size_t)n*32 + lane];
        mx.x = fmaxf(mx.x, v.x); mx.y = fmaxf(mx.y, v.y);
        mx.z = fmaxf(mx.z, v.z); mx.w = fmaxf(mx.w, v.w);
        mn.x = fminf(mn.x, v.x); mn.y = fminf(mn.y, v.y);
        mn.z = fminf(mn.z, v.z); mn.w = fminf(mn.w, v.w);
    }

    int cbase = lane*4;
    float vmx[4] = {mx.x, mx.y, mx.z, mx.w};
    float vmn[4] = {mn.x, mn.y, mn.z, mn.w};
    float4 r;
    float* rp = &r.x;
#pragma unroll
    for (int j = 0; j < 4; j++) {
        int c = cbase + j;
        float a  = d_rs[2*128 + c] * g2[c];
        float v  = (a >= 0.f) ? vmx[j] : vmn[j];
        rp[j] = fmaxf(0.f, fmaf(v - d_mu[2*128 + c], a, b2[c]));
    }
    reinterpret_cast<float4*>(out)[(size_t)warp*32 + lane] = r;
}

// ---------------- copy new_xyz into output head ----------------
__global__ void k_copy(const float* __restrict__ nxyz, float* __restrict__ out)
{
    int i = blockIdx.x*blockDim.x + threadIdx.x;
    if (i < BM_TOT*3) out[i] = nxyz[i];
}

// ---------------- launch ----------------
extern "C" void kernel_launch(void* const* d_in, const int* in_sizes, int n_in,
                              void* d_out, int out_size)
{
    const float* xyz    = (const float*)d_in[0];
    const float* points = (const float*)d_in[1];
    const float* nxyz   = (const float*)d_in[2];
    const float* W0     = (const float*)d_in[3];
    const float* g0     = (const float*)d_in[4];
    const float* b0     = (const float*)d_in[5];
    const float* W1     = (const float*)d_in[6];
    const float* g1     = (const float*)d_in[7];
    const float* b1     = (const float*)d_in[8];
    const float* W2     = (const float*)d_in[9];
    const float* g2     = (const float*)d_in[10];
    const float* b2     = (const float*)d_in[11];
    float* out = (float*)d_out;

    k_prep<<<ROWS_TOT/256, 256>>>(xyz);
    k_ballquery<<<BM_TOT/8, 256>>>(nxyz);

    // layer 0: 67 -> 64
    k_mlp<67, 64, 4, 0><<<ROWS_TOT/16, 256>>>(W0, nullptr, nullptr, xyz, points);
    k_stats<64, 0><<<NBLK_STATS, 256>>>();
    k_finalize<64><<<1, 128>>>(0);

    // layer 1: 64 -> 64 (applies affine0+relu on load)
    k_mlp<64, 64, 4, 1><<<ROWS_TOT/16, 256>>>(W1, g0, b0, nullptr, nullptr);
    k_stats<64, 1><<<NBLK_STATS, 256>>>();
    k_finalize<64><<<1, 128>>>(1);

    // layer 2: 64 -> 128 (applies affine1+relu on load)
    k_mlp<64, 128, 8, 2><<<ROWS_TOT/16, 256>>>(W2, g1, b1, nullptr, nullptr);
    k_stats<128, 2><<<NBLK_STATS, 256>>>();
    k_finalize<128><<<1, 128>>>(2);

    // pool + final BN/relu, and new_xyz passthrough
    k_maxpool<<<BM_TOT/8, 256>>>(g2, b2, out + (size_t)BM_TOT*3);
    k_copy<<<(BM_TOT*3 + 255)/256, 256>>>(nxyz, out);
}

// round 4
// speedup vs baseline: 3.1665x; 2.9110x over previous
#include <cuda_runtime.h>

// Problem constants (fixed by setup_inputs)
#define BATCH 16
#define NPTS  4096
#define MQ    1024
#define KNB   32
#define ROWS_TOT (BATCH*NPTS)      // 65536 source-point rows
#define BM_TOT   (BATCH*MQ)        // 16384 query points
#define CNT_TOT  (BATCH*MQ*KNB)    // 524288 gathered slots (BN denominator)
#define NBLK_STATS 1024
#define WSTRIDE 68                 // padded smem weight row stride (bank-conflict-free)

// ---------------- device scratch (static, no allocation) ----------------
__device__ int d_inds[BM_TOT*KNB];                    // ball-query neighbor indices
__device__ int d_cnt[ROWS_TOT];                       // multiplicity of each (b,n)
__device__ float d_sx[ROWS_TOT], d_sy[ROWS_TOT], d_sz[ROWS_TOT], d_pn[ROWS_TOT];
__device__ __align__(16) float d_z0[ROWS_TOT*64];     // raw layer-0 output per (b,n)
__device__ __align__(16) float d_z1[ROWS_TOT*64];     // raw layer-1 output
__device__ __align__(16) float d_z2[ROWS_TOT*128];    // raw layer-2 output
__device__ double d_part[NBLK_STATS*256];             // per-block stats partials (s | s2)
__device__ float d_mu[3*128];
__device__ float d_rs[3*128];

// ---------------- kernel 0: SoA transpose + |p|^2 + zero counters ----------------
__global__ void k_prep(const float* __restrict__ xyz)
{
    int i = blockIdx.x*blockDim.x + threadIdx.x;
    if (i >= ROWS_TOT) return;
    float x = xyz[3*i+0], y = xyz[3*i+1], z = xyz[3*i+2];
    d_sx[i] = x; d_sy[i] = y; d_sz[i] = z;
    d_pn[i] = x*x + y*y + z*z;
    d_cnt[i] = 0;
}

// ---------------- kernel 1: ball query (warp per query) ----------------
__global__ __launch_bounds__(256)
void k_ballquery(const float* __restrict__ nxyz)
{
    int lane = threadIdx.x & 31;
    int q = (blockIdx.x*blockDim.x + threadIdx.x) >> 5;   // query id in [0, BM_TOT)
    int b = q / MQ;
    int nb = b * NPTS;

    const float* qp = nxyz + (size_t)q*3;
    float qx = qp[0], qy = qp[1], qz = qp[2];
    float qn = qx*qx + qy*qy + qz*qz;

    int* my = d_inds + (size_t)q*KNB;
    int cnt = 0;
    int first = NPTS - 1;
    bool have_first = false;

    for (int base = 0; base < NPTS; base += 32) {
        int n = base + lane;
        float d2 = fmaf(-2.0f*qx, d_sx[nb+n],
                   fmaf(-2.0f*qy, d_sy[nb+n],
                   fmaf(-2.0f*qz, d_sz[nb+n], qn + d_pn[nb+n])));
        bool hit = d2 <= 0.25f;
        unsigned msk = __ballot_sync(0xffffffffu, hit);
        int pos = cnt + __popc(msk & ((1u << lane) - 1u));
        if (hit && pos < KNB) {
            my[pos] = n;
            atomicAdd(&d_cnt[nb+n], 1);
        }
        if (!have_first && msk) { first = base + __ffs(msk) - 1; have_first = true; }
        cnt += __popc(msk);
        if (cnt >= KNB) break;
    }

    if (cnt < KNB) {
        if (lane >= cnt) my[lane] = first;
        if (lane == 0) atomicAdd(&d_cnt[nb+first], KNB - cnt);
    }
}

// ---------------- MLP layer: per-source-point GEMM ----------------
// LAYER 0: feat = concat(xyz, points)            (CIN=67) -> d_z0
// LAYER 1: feat = relu(affine0(d_z0))            (CIN=64) -> d_z1
// LAYER 2: feat = relu(affine1(d_z1))            (CIN=64) -> d_z2
// Weights staged global->smem coalesced (padded stride 68 = conflict-free),
// then per-thread rows pulled into registers. Features in smem, broadcast LDS.
template<int CIN, int COUT, int RPT, int LAYER>
__global__ __launch_bounds__(256)
void k_mlp(const float* __restrict__ W,
           const float* __restrict__ ga, const float* __restrict__ be,
           const float* __restrict__ xyz, const float* __restrict__ pts)
{
    constexpr int CP4 = (CIN + 3) / 4;
    constexpr int CP  = CP4 * 4;
    constexpr int GROUPS = 256 / COUT;
    constexpr int ROWS = GROUPS * RPT;

    const float* zin = (LAYER == 2) ? d_z1 : d_z0;       // unused for LAYER 0
    float* zout = (LAYER == 0) ? d_z0 : ((LAYER == 1) ? d_z1 : d_z2);
    const float* mu = d_mu + (LAYER - 1) * 128;           // unused for LAYER 0
    const float* rs = d_rs + (LAYER - 1) * 128;

    __shared__ __align__(16) float sfeat[ROWS * CP];
    __shared__ __align__(16) float sW[COUT * WSTRIDE];
    int tid  = threadIdx.x;
    int row0 = blockIdx.x * ROWS;

    // coalesced weight staging: consecutive tid -> consecutive global floats
    for (int idx = tid; idx < COUT * CIN; idx += 256) {
        int r = idx / CIN, c = idx % CIN;
        sW[r*WSTRIDE + c] = W[idx];
    }
    // zero-pad columns CIN..CP-1 (only matters when CP > CIN)
    if (CP > CIN) {
        for (int r = tid; r < COUT; r += 256)
#pragma unroll
            for (int c = CIN; c < CP; c++) sW[r*WSTRIDE + c] = 0.f;
    }

    // cooperative feature staging
    for (int idx = tid; idx < ROWS * CP; idx += 256) {
        int r = idx / CP, c = idx % CP;
        int row = row0 + r;
        float v = 0.f;
        if (LAYER == 0) {
            if (c < 3)        v = xyz[(size_t)row*3 + c];
            else if (c < 67)  v = pts[(size_t)row*64 + (c - 3)];
        } else {
            if (c < CIN) {
                float a = rs[c] * ga[c];
                v = fmaxf(0.f, fmaf(zin[(size_t)row*CIN + c] - mu[c], a, be[c]));
            }
        }
        sfeat[idx] = v;
    }
    __syncthreads();

    // pull this thread's weight row into registers (conflict-free LDS.128)
    int o  = tid % COUT;
    int rg = tid / COUT;
    float4 wreg[CP4];
#pragma unroll
    for (int i = 0; i < CP4; i++)
        wreg[i] = *reinterpret_cast<const float4*>(&sW[o*WSTRIDE + 4*i]);

    float acc[RPT];
#pragma unroll
    for (int j = 0; j < RPT; j++) acc[j] = 0.f;

#pragma unroll
    for (int i = 0; i < CP4; i++) {
        float4 w = wreg[i];
#pragma unroll
        for (int j = 0; j < RPT; j++) {
            const float4 f = *reinterpret_cast<const float4*>(
                &sfeat[(rg*RPT + j)*CP + 4*i]);
            acc[j] = fmaf(w.x, f.x, acc[j]);
            acc[j] = fmaf(w.y, f.y, acc[j]);
            acc[j] = fmaf(w.z, f.z, acc[j]);
            acc[j] = fmaf(w.w, f.w, acc[j]);
        }
    }
#pragma unroll
    for (int j = 0; j < RPT; j++)
        zout[(size_t)(row0 + rg*RPT + j)*COUT + o] = acc[j];
}

// ---------------- count-weighted BN statistics ----------------
// Pass A: 1024 blocks produce per-block double partials (deterministic order).
template<int COUT, int LAYER>
__global__ __launch_bounds__(256)
void k_stats()
{
    const float* z = (LAYER == 0) ? d_z0 : ((LAYER == 1) ? d_z1 : d_z2);
    constexpr int G  = 256 / COUT;
    constexpr int RB = ROWS_TOT / NBLK_STATS;   // 64 rows per block
    int tid = threadIdx.x;
    int o   = tid % COUT;
    int r0  = tid / COUT;

    double s = 0.0, s2 = 0.0;
    for (int r = r0; r < RB; r += G) {
        int row = blockIdx.x*RB + r;
        double w = (double)d_cnt[row];
        double v = (double)z[(size_t)row*COUT + o];
        s  += w * v;
        s2 += w * v * v;
    }
    __shared__ double ss[256], ss2[256];
    ss[tid] = s; ss2[tid] = s2;
    __syncthreads();
    if (tid < COUT) {
        double ts = 0.0, t2 = 0.0;
        for (int g = 0; g < G; g++) { ts += ss[tid + g*COUT]; t2 += ss2[tid + g*COUT]; }
        d_part[blockIdx.x*256 + tid]       = ts;
        d_part[blockIdx.x*256 + 128 + tid] = t2;
    }
}

// Pass B: 8-way split fixed-order reduction over block partials -> mu, rsigma.
template<int COUT>
__global__ __launch_bounds__(1024)
void k_finalize(int layer)
{
    __shared__ double ss[1024], ss2[1024];
    int tid = threadIdx.x;
    int c = tid & 127;
    int t = tid >> 7;            // 8 groups of 128 blocks each
    double s = 0.0, s2 = 0.0;
    if (c < COUT) {
        for (int b = t*128; b < (t+1)*128; b++) {
            s  += d_part[b*256 + c];
            s2 += d_part[b*256 + 128 + c];
        }
    }
    ss[tid] = s; ss2[tid] = s2;
    __syncthreads();
    if (tid < COUT) {
        double ts = 0.0, t2 = 0.0;
#pragma unroll
        for (int g = 0; g < 8; g++) { ts += ss[tid + g*128]; t2 += ss2[tid + g*128]; }
        double mu  = ts / (double)CNT_TOT;
        double var = t2 / (double)CNT_TOT - mu*mu;
        d_mu[layer*128 + tid] = (float)mu;
        d_rs[layer*128 + tid] = (float)(1.0 / sqrt(var + 1e-5));
    }
}

// ---------------- max-pool + final BN + ReLU ----------------
__global__ __launch_bounds__(256)
void k_maxpool(const float* __restrict__ g2, const float* __restrict__ b2,
               float* __restrict__ out)
{
    int warp = (blockIdx.x*blockDim.x + threadIdx.x) >> 5;
    int lane = threadIdx.x & 31;
    int b = warp / MQ;
    int myind = d_inds[warp*KNB + lane];

    float4 mx = make_float4(-3.4e38f, -3.4e38f, -3.4e38f, -3.4e38f);
    float4 mn = make_float4( 3.4e38f,  3.4e38f,  3.4e38f,  3.4e38f);
    const float4* zb = reinterpret_cast<const float4*>(d_z2) + (size_t)b*NPTS*32;
#pragma unroll 8
    for (int k = 0; k < KNB; k++) {
        int n = __shfl_sync(0xffffffffu, myind, k);
        float4 v = zb[(size_t)n*32 + lane];
        mx.x = fmaxf(mx.x, v.x); mx.y = fmaxf(mx.y, v.y);
        mx.z = fmaxf(mx.z, v.z); mx.w = fmaxf(mx.w, v.w);
        mn.x = fminf(mn.x, v.x); mn.y = fminf(mn.y, v.y);
        mn.z = fminf(mn.z, v.z); mn.w = fminf(mn.w, v.w);
    }

    int cbase = lane*4;
    float vmx[4] = {mx.x, mx.y, mx.z, mx.w};
    float vmn[4] = {mn.x, mn.y, mn.z, mn.w};
    float4 r;
    float* rp = &r.x;
#pragma unroll
    for (int j = 0; j < 4; j++) {
        int c = cbase + j;
        float a  = d_rs[2*128 + c] * g2[c];
        float v  = (a >= 0.f) ? vmx[j] : vmn[j];
        rp[j] = fmaxf(0.f, fmaf(v - d_mu[2*128 + c], a, b2[c]));
    }
    reinterpret_cast<float4*>(out)[(size_t)warp*32 + lane] = r;
}

// ---------------- copy new_xyz into output head ----------------
__global__ void k_copy(const float* __restrict__ nxyz, float* __restrict__ out)
{
    int i = blockIdx.x*blockDim.x + threadIdx.x;
    if (i < BM_TOT*3) out[i] = nxyz[i];
}

// ---------------- launch ----------------
extern "C" void kernel_launch(void* const* d_in, const int* in_sizes, int n_in,
                              void* d_out, int out_size)
{
    const float* xyz    = (const float*)d_in[0];
    const float* points = (const float*)d_in[1];
    const float* nxyz   = (const float*)d_in[2];
    const float* W0     = (const float*)d_in[3];
    const float* g0     = (const float*)d_in[4];
    const float* b0     = (const float*)d_in[5];
    const float* W1     = (const float*)d_in[6];
    const float* g1     = (const float*)d_in[7];
    const float* b1     = (const float*)d_in[8];
    const float* W2     = (const float*)d_in[9];
    const float* g2     = (const float*)d_in[10];
    const float* b2     = (const float*)d_in[11];
    float* out = (float*)d_out;

    k_prep<<<ROWS_TOT/256, 256>>>(xyz);
    k_ballquery<<<BM_TOT/8, 256>>>(nxyz);

    // layer 0: 67 -> 64
    k_mlp<67, 64, 4, 0><<<ROWS_TOT/16, 256>>>(W0, nullptr, nullptr, xyz, points);
    k_stats<64, 0><<<NBLK_STATS, 256>>>();
    k_finalize<64><<<1, 1024>>>(0);

    // layer 1: 64 -> 64 (applies affine0+relu on load)
    k_mlp<64, 64, 4, 1><<<ROWS_TOT/16, 256>>>(W1, g0, b0, nullptr, nullptr);
    k_stats<64, 1><<<NBLK_STATS, 256>>>();
    k_finalize<64><<<1, 1024>>>(1);

    // layer 2: 64 -> 128 (applies affine1+relu on load)
    k_mlp<64, 128, 8, 2><<<ROWS_TOT/16, 256>>>(W2, g1, b1, nullptr, nullptr);
    k_stats<128, 2><<<NBLK_STATS, 256>>>();
    k_finalize<128><<<1, 1024>>>(2);

    // pool + final BN/relu, and new_xyz passthrough
    k_maxpool<<<BM_TOT/8, 256>>>(g2, b2, out + (size_t)BM_TOT*3);
    k_copy<<<(BM_TOT*3 + 255)/256, 256>>>(nxyz, out);
}